// round 8
// baseline (speedup 1.0000x reference)
#include <cuda_runtime.h>

#define Bd 8
#define Td 512
#define Cd 512
#define NHd 8
#define HDd 64
#define Md (Bd * Td)            // 4096
#define QKVN (3 * Cd)           // 1536

__device__ float g_qkv[Md * QKVN];
__device__ float g_y[Md * Cd];

__device__ __forceinline__ unsigned f2tf(float f) {
    unsigned u; asm("cvt.rna.tf32.f32 %0, %1;" : "=r"(u) : "f"(f)); return u;
}
__device__ __forceinline__ void mma_tf32(float c[4],
    unsigned a0, unsigned a1, unsigned a2, unsigned a3,
    unsigned b0, unsigned b1)
{
    asm volatile(
        "mma.sync.aligned.m16n8k8.row.col.f32.tf32.tf32.f32 "
        "{%0,%1,%2,%3}, {%4,%5,%6,%7}, {%8,%9}, {%0,%1,%2,%3};"
        : "+f"(c[0]), "+f"(c[1]), "+f"(c[2]), "+f"(c[3])
        : "r"(a0), "r"(a1), "r"(a2), "r"(a3), "r"(b0), "r"(b1));
}

// Fragment-major smem stores.
// A-fragment (m16 x k8): word idx = frag*128 + lane*4 + reg
//   lane = (r&7)*4 + (c&3);  reg = ((r>>3)&1) + ((c>>2)&1)*2
__device__ __forceinline__ void stA4(unsigned* f, int NK, int r, int c0, float4 v) {
    int base = ((r >> 4) * NK + (c0 >> 3)) * 128 + ((r & 7) << 4)
             + ((r >> 3) & 1) + (((c0 >> 2) & 1) << 1);
    f[base] = f2tf(v.x); f[base + 4] = f2tf(v.y);
    f[base + 8] = f2tf(v.z); f[base + 12] = f2tf(v.w);
}
// B-fragment (n8 x k8): word idx = frag*64 + lane*2 + reg
//   lane = (n&7)*4 + (c&3);  reg = (c>>2)&1
__device__ __forceinline__ void stB4(unsigned* f, int NK, int n, int c0, float4 v) {
    int base = ((n >> 3) * NK + (c0 >> 3)) * 64 + ((n & 7) << 3) + ((c0 >> 2) & 1);
    f[base] = f2tf(v.x); f[base + 2] = f2tf(v.y);
    f[base + 4] = f2tf(v.z); f[base + 6] = f2tf(v.w);
}
// B-fragment store when the float4 runs along n (V tiles: n=d, k=key)
__device__ __forceinline__ void stBV4(unsigned* f, int NK, int d0, int key, float4 v) {
    int base = ((d0 >> 3) * NK + (key >> 3)) * 64 + ((d0 & 7) << 3)
             + ((key & 3) << 1) + ((key >> 2) & 1);
    f[base] = f2tf(v.x); f[base + 8] = f2tf(v.y);
    f[base + 16] = f2tf(v.z); f[base + 24] = f2tf(v.w);
}

// ---------------------------------------------------------------------------
// tf32 SGEMM, fragment-major smem. BM x 64 tile, BK=32, 256 threads.
// ---------------------------------------------------------------------------
template<int BM>
__global__ __launch_bounds__(256) void sgemm_bias_kernel(
    const float* __restrict__ A, const float* __restrict__ W,
    const float* __restrict__ bias, float* __restrict__ out,
    int Kdim, int Ndim)
{
    constexpr int MI = BM / 64;            // m-subtiles per warp
    constexpr int AL = BM / 32;            // A float4 loads per thread
    __shared__ unsigned Af[BM * 32];       // (BM/16)*4 frags * 128
    __shared__ unsigned Bf[2048];          // 8*4 frags * 64
    const int tid = threadIdx.x;
    const int lane = tid & 31, warp = tid >> 5;
    const int m0 = blockIdx.y * BM, n0 = blockIdx.x << 6;
    const int nsb = (warp >> 2) << 2;      // B n-subtile base (0 or 4)

    const int lrow = tid >> 3;             // 0..31
    const int lk4 = (tid & 7) << 2;        // 0,4,..,28

    float c[MI][4][4] = {};
    float4 avr[AL], bvr[2];

    #pragma unroll
    for (int i = 0; i < AL; i++)
        avr[i] = *(const float4*)&A[(size_t)(m0 + lrow + (i << 5)) * Kdim + lk4];
    #pragma unroll
    for (int i = 0; i < 2; i++)
        bvr[i] = *(const float4*)&W[(size_t)(n0 + lrow + (i << 5)) * Kdim + lk4];

    for (int k0 = 0; k0 < Kdim; k0 += 32) {
        #pragma unroll
        for (int i = 0; i < AL; i++)
            stA4(Af, 4, lrow + (i << 5), lk4, avr[i]);
        #pragma unroll
        for (int i = 0; i < 2; i++)
            stB4(Bf, 4, lrow + (i << 5), lk4, bvr[i]);
        __syncthreads();

        if (k0 + 32 < Kdim) {
            #pragma unroll
            for (int i = 0; i < AL; i++)
                avr[i] = *(const float4*)&A[(size_t)(m0 + lrow + (i << 5)) * Kdim + k0 + 32 + lk4];
            #pragma unroll
            for (int i = 0; i < 2; i++)
                bvr[i] = *(const float4*)&W[(size_t)(n0 + lrow + (i << 5)) * Kdim + k0 + 32 + lk4];
        }

        #pragma unroll
        for (int ks = 0; ks < 4; ks++) {
            uint4 av[MI];
            #pragma unroll
            for (int i = 0; i < MI; i++) {
                int mi = (warp & 3) * MI + i;
                av[i] = *(const uint4*)&Af[(mi * 4 + ks) * 128 + (lane << 2)];
            }
            #pragma unroll
            for (int j = 0; j < 4; j++) {
                uint2 bv = *(const uint2*)&Bf[((nsb + j) * 4 + ks) * 64 + (lane << 1)];
                #pragma unroll
                for (int i = 0; i < MI; i++)
                    mma_tf32(c[i][j], av[i].x, av[i].y, av[i].z, av[i].w, bv.x, bv.y);
            }
        }
        __syncthreads();
    }

    const int g = lane >> 2, tig = lane & 3;
    #pragma unroll
    for (int i = 0; i < MI; i++) {
        #pragma unroll
        for (int j = 0; j < 4; j++) {
            int row = m0 + ((warp & 3) * MI + i) * 16 + g;
            int col = n0 + (nsb + j) * 8 + (tig << 1);
            float b0 = bias[col], b1 = bias[col + 1];
            *(float2*)&out[(size_t)row * Ndim + col] =
                make_float2(c[i][j][0] + b0, c[i][j][1] + b1);
            *(float2*)&out[(size_t)(row + 8) * Ndim + col] =
                make_float2(c[i][j][2] + b0, c[i][j][3] + b1);
        }
    }
}

// ---------------------------------------------------------------------------
// LayerNorm q,k (unchanged)
// ---------------------------------------------------------------------------
__global__ __launch_bounds__(256) void ln_qk_kernel(
    float* __restrict__ qkv,
    const float* __restrict__ qg, const float* __restrict__ qb,
    const float* __restrict__ kg, const float* __restrict__ kb)
{
    const int bt = blockIdx.x;
    float* row = qkv + (size_t)bt * QKVN;
    const int tid = threadIdx.x;
    const int lane = tid & 31, w = tid >> 5;
    __shared__ float sh_s[8], sh_ss[8];

    #pragma unroll
    for (int seg = 0; seg < 2; seg++) {
        float* p = row + seg * Cd;
        const float* gam = seg ? kg : qg;
        const float* bet = seg ? kb : qb;
        float x0 = p[tid], x1 = p[tid + 256];
        float s = x0 + x1;
        float ss = x0 * x0 + x1 * x1;
        #pragma unroll
        for (int o = 16; o; o >>= 1) {
            s  += __shfl_xor_sync(0xffffffffu, s, o);
            ss += __shfl_xor_sync(0xffffffffu, ss, o);
        }
        if (lane == 0) { sh_s[w] = s; sh_ss[w] = ss; }
        __syncthreads();
        float tot = 0.f, tot2 = 0.f;
        #pragma unroll
        for (int i = 0; i < 8; i++) { tot += sh_s[i]; tot2 += sh_ss[i]; }
        float mu = tot * (1.0f / 512.0f);
        float var = tot2 * (1.0f / 512.0f) - mu * mu;
        float rstd = rsqrtf(var + 1e-5f);
        p[tid]       = (x0 - mu) * rstd * gam[tid]       + bet[tid];
        p[tid + 256] = (x1 - mu) * rstd * gam[tid + 256] + bet[tid + 256];
        __syncthreads();
    }
}

// ---------------------------------------------------------------------------
// Flash attention, fragment-major operands + register-resident softmax.
// smem words: QF 4096 | RF 8192 (rel x2; V reuses slot 0) | KF/PF 4096 |
//             pcat 8448 | pm 128 | ps 128   -> 100352 bytes
// ---------------------------------------------------------------------------
#define PCP 132
#define ATTN_SMEM ((16384 + 8448 + 256) * 4)

__global__ __launch_bounds__(256, 2) void attn_kernel(
    const float* __restrict__ qkv,
    const float* __restrict__ rel_emb,
    float* __restrict__ yout)
{
    const int blk = blockIdx.x;
    const int qb = 7 - (blk & 7);        // heavy blocks first
    const int h  = (blk >> 3) & 7;
    const int b  = blk >> 6;
    const int q0 = qb << 6;
    const int ntiles = qb + 1;

    extern __shared__ unsigned smu[];
    unsigned* QF = smu;                  // Q A-frags
    unsigned* RF = smu + 4096;           // rel B-frags (2 tiles); V B-frags reuse slot 0
    unsigned* KF = smu + 12288;          // K B-frags, later P A-frags
    float* pcat = (float*)(smu + 16384);
    float* pm   = (float*)(smu + 16384 + 8448);
    float* ps   = pm + 128;

    const int tid = threadIdx.x;
    const int lane = tid & 31, warp = tid >> 5;
    const int g = lane >> 2, tig = lane & 3;
    const int qm = (warp & 3) << 4;      // warp q-row base
    const int wn = (warp >> 2) << 5;     // warp n-col base
    const int nsb = (warp >> 2) << 2;    // B n-subtile base
    const int wcol = warp >> 2;

    const int lr = tid >> 4;             // 0..15
    const int lc4 = (tid & 15) << 2;     // 0..60

    // ---- Q block as A-fragments ----
    {
        const float* qbase = qkv + (size_t)(b * Td + q0) * QKVN + h * HDd;
        #pragma unroll
        for (int i = 0; i < 4; i++) {
            int r = lr + (i << 4);
            stA4(QF, 8, r, lc4, *(const float4*)&qbase[(size_t)r * QKVN + lc4]);
        }
    }

    float o[4][4] = {};
    float m0_ = -1e30f, m1_ = -1e30f, l0_ = 0.f, l1_ = 0.f;
    const float scale = 0.125f;
    const int r0 = qm + g, r1 = qm + g + 8;

    for (int kt = 0; kt < ntiles; kt++) {
        const int D = q0 - (kt << 6);
        const bool haveLo = (D != 0);

        // ---- load K + rel band as B-fragments ----
        {
            const float* kbase = qkv + (size_t)(b * Td + (kt << 6)) * QKVN + Cd + h * HDd;
            #pragma unroll
            for (int i = 0; i < 4; i++) {
                int r = lr + (i << 4);
                stB4(KF, 8, r, lc4, *(const float4*)&kbase[(size_t)r * QKVN + lc4]);
            }
            #pragma unroll
            for (int i = 0; i < 8; i++) {
                int rr = lr + (i << 4);              // 0..127
                int delta = D - 64 + rr;
                if (delta >= 0) {
                    float4 v = *(const float4*)&rel_emb[(size_t)delta * Cd + h * HDd + lc4];
                    stB4(RF + ((rr >> 6) << 12), 8, rr & 63, lc4, v);
                }
            }
        }
        __syncthreads();   // (a)

        // ---- MMA: S = Q K^T ; P = Q rel^T ----
        float cS[4][4] = {};
        float cP1[4][4] = {};
        float cP0[4][4] = {};
        #pragma unroll
        for (int ks = 0; ks < 8; ks++) {
            uint4 aq = *(const uint4*)&QF[(((warp & 3) << 3) + ks) * 128 + (lane << 2)];
            #pragma unroll
            for (int j = 0; j < 4; j++) {
                int fb = (((nsb + j) << 3) + ks) * 64 + (lane << 1);
                uint2 bk = *(const uint2*)&KF[fb];
                mma_tf32(cS[j], aq.x, aq.y, aq.z, aq.w, bk.x, bk.y);
                uint2 bh = *(const uint2*)&RF[4096 + fb];
                mma_tf32(cP1[j], aq.x, aq.y, aq.z, aq.w, bh.x, bh.y);
                if (haveLo) {
                    uint2 bl = *(const uint2*)&RF[fb];
                    mma_tf32(cP0[j], aq.x, aq.y, aq.z, aq.w, bl.x, bl.y);
                }
            }
        }
        // write pcat (rel bias, per-q row band of 128 deltas)
        #pragma unroll
        for (int j = 0; j < 4; j++) {
            int col = wn + (j << 3) + (tig << 1);
            if (haveLo) {
                *(float2*)&pcat[r0 * PCP + col] = make_float2(cP0[j][0], cP0[j][1]);
                *(float2*)&pcat[r1 * PCP + col] = make_float2(cP0[j][2], cP0[j][3]);
            }
            *(float2*)&pcat[r0 * PCP + 64 + col] = make_float2(cP1[j][0], cP1[j][1]);
            *(float2*)&pcat[r1 * PCP + 64 + col] = make_float2(cP1[j][2], cP1[j][3]);
        }
        __syncthreads();   // (b)  pcat visible; K/rel reads done

        // ---- V tile as B-fragments (n=d, k=key), overwrites rel slot 0 ----
        {
            const float* vbase = qkv + (size_t)(b * Td + (kt << 6)) * QKVN + 2 * Cd + h * HDd;
            #pragma unroll
            for (int i = 0; i < 4; i++) {
                int key = lr + (i << 4);
                stBV4(RF, 8, lc4, key, *(const float4*)&vbase[(size_t)key * QKVN + lc4]);
            }
        }

        // ---- scores in registers: mask + bias + scale ----
        float s_[4][4];
        #pragma unroll
        for (int j = 0; j < 4; j++) {
            #pragma unroll
            for (int u = 0; u < 2; u++) {
                int c = wn + (j << 3) + (tig << 1) + u;
                s_[j][u] = (r0 - c + D >= 0)
                    ? (cS[j][u] + pcat[r0 * PCP + 64 + r0 - c]) * scale : -1e30f;
                s_[j][2 + u] = (r1 - c + D >= 0)
                    ? (cS[j][2 + u] + pcat[r1 * PCP + 64 + r1 - c]) * scale : -1e30f;
            }
        }
        // warp-partial row max (across tig lanes)
        float mx0 = -1e30f, mx1 = -1e30f;
        #pragma unroll
        for (int j = 0; j < 4; j++) {
            mx0 = fmaxf(mx0, fmaxf(s_[j][0], s_[j][1]));
            mx1 = fmaxf(mx1, fmaxf(s_[j][2], s_[j][3]));
        }
        #pragma unroll
        for (int oo = 1; oo <= 2; oo <<= 1) {
            mx0 = fmaxf(mx0, __shfl_xor_sync(0xffffffffu, mx0, oo));
            mx1 = fmaxf(mx1, __shfl_xor_sync(0xffffffffu, mx1, oo));
        }
        if (tig == 0) { pm[wcol * 64 + r0] = mx0; pm[wcol * 64 + r1] = mx1; }
        __syncthreads();   // (c)

        float tm0 = fmaxf(mx0, pm[(1 - wcol) * 64 + r0]);
        float tm1 = fmaxf(mx1, pm[(1 - wcol) * 64 + r1]);
        float mn0 = fmaxf(m0_, tm0), mn1 = fmaxf(m1_, tm1);
        float al0 = __expf(m0_ - mn0), al1 = __expf(m1_ - mn1);
        m0_ = mn0; m1_ = mn1;

        // exp, P-fragment store, warp-partial sums
        float sum0 = 0.f, sum1 = 0.f;
        #pragma unroll
        for (int j = 0; j < 4; j++) {
            #pragma unroll
            for (int u = 0; u < 2; u++) {
                int c = wn + (j << 3) + (tig << 1) + u;
                float p0 = __expf(s_[j][u] - mn0);
                float p1 = __expf(s_[j][2 + u] - mn1);
                sum0 += p0; sum1 += p1;
                int wi = (((qm >> 4) << 3) + (c >> 3)) * 128
                       + ((g << 2) + (c & 3)) * 4 + (((c >> 2) & 1) << 1);
                uint2 pp = make_uint2(f2tf(p0), f2tf(p1));
                *(uint2*)&KF[wi] = pp;          // P in A-fragment layout
            }
        }
        #pragma unroll
        for (int oo = 1; oo <= 2; oo <<= 1) {
            sum0 += __shfl_xor_sync(0xffffffffu, sum0, oo);
            sum1 += __shfl_xor_sync(0xffffffffu, sum1, oo);
        }
        if (tig == 0) { ps[wcol * 64 + r0] = sum0; ps[wcol * 64 + r1] = sum1; }
        __syncthreads();   // (d)  P frags + sums + V frags visible

        l0_ = l0_ * al0 + sum0 + ps[(1 - wcol) * 64 + r0];
        l1_ = l1_ * al1 + sum1 + ps[(1 - wcol) * 64 + r1];

        #pragma unroll
        for (int j = 0; j < 4; j++) {
            o[j][0] *= al0; o[j][1] *= al0;
            o[j][2] *= al1; o[j][3] *= al1;
        }
        // ---- O += P V ----
        #pragma unroll
        for (int ks = 0; ks < 8; ks++) {
            uint4 ap = *(const uint4*)&KF[(((warp & 3) << 3) + ks) * 128 + (lane << 2)];
            #pragma unroll
            for (int j = 0; j < 4; j++) {
                uint2 bv = *(const uint2*)&RF[(((nsb + j) << 3) + ks) * 64 + (lane << 1)];
                mma_tf32(o[j], ap.x, ap.y, ap.z, ap.w, bv.x, bv.y);
            }
        }
        __syncthreads();   // (e)
    }

    // ---- finalize ----
    {
        float inv0 = 1.0f / l0_, inv1 = 1.0f / l1_;
        int row = b * Td + q0 + r0;
        #pragma unroll
        for (int j = 0; j < 4; j++) {
            int col = h * HDd + wn + (j << 3) + (tig << 1);
            *(float2*)&yout[(size_t)row * Cd + col] =
                make_float2(o[j][0] * inv0, o[j][1] * inv0);
            *(float2*)&yout[(size_t)(row + 8) * Cd + col] =
                make_float2(o[j][2] * inv1, o[j][3] * inv1);
        }
    }
}

// ---------------------------------------------------------------------------
extern "C" void kernel_launch(void* const* d_in, const int* in_sizes, int n_in,
                              void* d_out, int out_size)
{
    const float* x      = (const float*)d_in[0];
    const float* w_attn = (const float*)d_in[1];
    const float* b_attn = (const float*)d_in[2];
    const float* w_proj = (const float*)d_in[3];
    const float* b_proj = (const float*)d_in[4];
    const float* qg     = (const float*)d_in[5];
    const float* qbeta  = (const float*)d_in[6];
    const float* kg     = (const float*)d_in[7];
    const float* kbeta  = (const float*)d_in[8];
    const float* rel    = (const float*)d_in[9];
    float* out = (float*)d_out;

    float *qkv_p, *y_p;
    cudaGetSymbolAddress((void**)&qkv_p, g_qkv);
    cudaGetSymbolAddress((void**)&y_p, g_y);

    cudaFuncSetAttribute(attn_kernel,
                         cudaFuncAttributeMaxDynamicSharedMemorySize, ATTN_SMEM);

    // 1) QKV projection
    {
        dim3 grid(QKVN / 64, Md / 128);
        sgemm_bias_kernel<128><<<grid, 256>>>(x, w_attn, b_attn, qkv_p, Cd, QKVN);
    }
    // 2) LayerNorm q,k in place
    ln_qk_kernel<<<Md, 256>>>(qkv_p, qg, qbeta, kg, kbeta);
    // 3) Flash attention
    attn_kernel<<<Bd * NHd * (Td / 64), 256, ATTN_SMEM>>>(qkv_p, rel, y_p);
    // 4) Output projection
    {
        dim3 grid(Cd / 64, Md / 64);
        sgemm_bias_kernel<64><<<grid, 256>>>(y_p, w_proj, b_proj, out, Cd, Cd);
    }
}

// round 12
// speedup vs baseline: 2.1040x; 2.1040x over previous
#include <cuda_runtime.h>
#include <cuda_fp16.h>

#define Bd 8
#define Td 512
#define Cd 512
#define NHd 8
#define HDd 64
#define Md (Bd * Td)            // 4096
#define QKVN (3 * Cd)           // 1536

__device__ float g_qkv[Md * QKVN];
__device__ float g_y[Md * Cd];

// pack two floats into half2 bits (lo, hi)
__device__ __forceinline__ unsigned f2h2(float lo, float hi) {
    unsigned u;
    asm("cvt.rn.f16x2.f32 %0, %1, %2;" : "=r"(u) : "f"(hi), "f"(lo));
    return u;
}
__device__ __forceinline__ uint2 pack4(float4 v) {
    return make_uint2(f2h2(v.x, v.y), f2h2(v.z, v.w));
}
__device__ __forceinline__ void mma_f16(float c[4],
    unsigned a0, unsigned a1, unsigned a2, unsigned a3,
    unsigned b0, unsigned b1)
{
    asm volatile(
        "mma.sync.aligned.m16n8k16.row.col.f32.f16.f16.f32 "
        "{%0,%1,%2,%3}, {%4,%5,%6,%7}, {%8,%9}, {%0,%1,%2,%3};"
        : "+f"(c[0]), "+f"(c[1]), "+f"(c[2]), "+f"(c[3])
        : "r"(a0), "r"(a1), "r"(a2), "r"(a3), "r"(b0), "r"(b1));
}

// ---------------------------------------------------------------------------
// fp16 SGEMM: out[m,n] = A[m,:]·W[n,:] + bias[n]
// BM x 64 tile, BK=32, 256 threads, warps 4(M)x2(N). Smem in half2 units,
// pitch 20 half2 (40 halfs) -> conflict-free frag reads (20g+tig distinct).
// ---------------------------------------------------------------------------
#define GP2 20
template<int BM>
__global__ __launch_bounds__(256) void sgemm_bias_kernel(
    const float* __restrict__ A, const float* __restrict__ W,
    const float* __restrict__ bias, float* __restrict__ out,
    int Kdim, int Ndim)
{
    constexpr int MI = BM / 64;
    constexpr int AL = BM / 32;
    __shared__ unsigned As[BM * GP2];
    __shared__ unsigned Bs[64 * GP2];
    const int tid = threadIdx.x;
    const int lane = tid & 31, warp = tid >> 5;
    const int g = lane >> 2, tig = lane & 3;
    const int wm = (warp & 3) * (BM / 4);
    const int wn = (warp >> 2) << 5;
    const int m0 = blockIdx.y * BM, n0 = blockIdx.x << 6;

    const int lrow = tid >> 3;             // 0..31
    const int lk4 = (tid & 7) << 2;        // halfs 0,4..28
    const int lk2 = lk4 >> 1;              // half2 idx

    float c[MI][4][4] = {};
    float4 avr[AL], bvr[2];

    #pragma unroll
    for (int i = 0; i < AL; i++)
        avr[i] = *(const float4*)&A[(size_t)(m0 + lrow + (i << 5)) * Kdim + lk4];
    #pragma unroll
    for (int i = 0; i < 2; i++)
        bvr[i] = *(const float4*)&W[(size_t)(n0 + lrow + (i << 5)) * Kdim + lk4];

    for (int k0 = 0; k0 < Kdim; k0 += 32) {
        #pragma unroll
        for (int i = 0; i < AL; i++)
            *(uint2*)&As[(lrow + (i << 5)) * GP2 + lk2] = pack4(avr[i]);
        #pragma unroll
        for (int i = 0; i < 2; i++)
            *(uint2*)&Bs[(lrow + (i << 5)) * GP2 + lk2] = pack4(bvr[i]);
        __syncthreads();

        if (k0 + 32 < Kdim) {
            #pragma unroll
            for (int i = 0; i < AL; i++)
                avr[i] = *(const float4*)&A[(size_t)(m0 + lrow + (i << 5)) * Kdim + k0 + 32 + lk4];
            #pragma unroll
            for (int i = 0; i < 2; i++)
                bvr[i] = *(const float4*)&W[(size_t)(n0 + lrow + (i << 5)) * Kdim + k0 + 32 + lk4];
        }

        #pragma unroll
        for (int ks = 0; ks < 2; ks++) {           // two k16 steps
            const int ko = ks << 3;                // half2 offset
            unsigned a[MI][4];
            #pragma unroll
            for (int i = 0; i < MI; i++) {
                int mb = wm + (i << 4);
                a[i][0] = As[(mb + g) * GP2 + ko + tig];
                a[i][1] = As[(mb + g + 8) * GP2 + ko + tig];
                a[i][2] = As[(mb + g) * GP2 + ko + 4 + tig];
                a[i][3] = As[(mb + g + 8) * GP2 + ko + 4 + tig];
            }
            #pragma unroll
            for (int j = 0; j < 4; j++) {
                int nb = wn + (j << 3) + g;
                unsigned b0 = Bs[nb * GP2 + ko + tig];
                unsigned b1 = Bs[nb * GP2 + ko + 4 + tig];
                #pragma unroll
                for (int i = 0; i < MI; i++)
                    mma_f16(c[i][j], a[i][0], a[i][1], a[i][2], a[i][3], b0, b1);
            }
        }
        __syncthreads();
    }

    #pragma unroll
    for (int i = 0; i < MI; i++) {
        #pragma unroll
        for (int j = 0; j < 4; j++) {
            int row = m0 + wm + (i << 4) + g;
            int col = n0 + wn + (j << 3) + (tig << 1);
            float b0 = bias[col], b1 = bias[col + 1];
            *(float2*)&out[(size_t)row * Ndim + col] =
                make_float2(c[i][j][0] + b0, c[i][j][1] + b1);
            *(float2*)&out[(size_t)(row + 8) * Ndim + col] =
                make_float2(c[i][j][2] + b0, c[i][j][3] + b1);
        }
    }
}

// ---------------------------------------------------------------------------
// LayerNorm q,k (unchanged)
// ---------------------------------------------------------------------------
__global__ __launch_bounds__(256) void ln_qk_kernel(
    float* __restrict__ qkv,
    const float* __restrict__ qg, const float* __restrict__ qb,
    const float* __restrict__ kg, const float* __restrict__ kb)
{
    const int bt = blockIdx.x;
    float* row = qkv + (size_t)bt * QKVN;
    const int tid = threadIdx.x;
    const int lane = tid & 31, w = tid >> 5;
    __shared__ float sh_s[8], sh_ss[8];

    #pragma unroll
    for (int seg = 0; seg < 2; seg++) {
        float* p = row + seg * Cd;
        const float* gam = seg ? kg : qg;
        const float* bet = seg ? kb : qb;
        float x0 = p[tid], x1 = p[tid + 256];
        float s = x0 + x1;
        float ss = x0 * x0 + x1 * x1;
        #pragma unroll
        for (int o = 16; o; o >>= 1) {
            s  += __shfl_xor_sync(0xffffffffu, s, o);
            ss += __shfl_xor_sync(0xffffffffu, ss, o);
        }
        if (lane == 0) { sh_s[w] = s; sh_ss[w] = ss; }
        __syncthreads();
        float tot = 0.f, tot2 = 0.f;
        #pragma unroll
        for (int i = 0; i < 8; i++) { tot += sh_s[i]; tot2 += sh_ss[i]; }
        float mu = tot * (1.0f / 512.0f);
        float var = tot2 * (1.0f / 512.0f) - mu * mu;
        float rstd = rsqrtf(var + 1e-5f);
        p[tid]       = (x0 - mu) * rstd * gam[tid]       + bet[tid];
        p[tid + 256] = (x1 - mu) * rstd * gam[tid + 256] + bet[tid + 256];
        __syncthreads();
    }
}

// ---------------------------------------------------------------------------
// Flash attention, fp16 MMA, plain half2 tile layouts (pitch 36 half2 = 72
// halfs -> bank = 4g+tig, conflict-free), register-resident softmax.
// smem words(4B): QF 2304 | RF 4608 (rel x2; V reuses slot0) | KF 2304 |
//                 PF 2304 | pcat 8448 | pm 128 | ps 128  = 80896 bytes
// ---------------------------------------------------------------------------
#define TP2 36
#define PCP 132
#define ATTN_SMEM ((2304 * 4 + 4608 + 8448 + 256) * 4)

__global__ __launch_bounds__(256, 2) void attn_kernel(
    const float* __restrict__ qkv,
    const float* __restrict__ rel_emb,
    float* __restrict__ yout)
{
    const int blk = blockIdx.x;
    const int qb = 7 - (blk & 7);        // heavy blocks first
    const int h  = (blk >> 3) & 7;
    const int b  = blk >> 6;
    const int q0 = qb << 6;
    const int ntiles = qb + 1;

    extern __shared__ unsigned smu[];
    unsigned* QF = smu;                  // Q [row][k] half2
    unsigned* RF = smu + 2304;           // rel tiles x2; V (transposed) reuses slot0
    unsigned* KF = smu + 6912;           // K [key][d] half2
    unsigned* PF = smu + 9216;           // probabilities [row][key] half2
    float* pcat = (float*)(smu + 11520);
    float* pm   = (float*)(smu + 19968);
    float* ps   = (float*)(smu + 20096);

    const int tid = threadIdx.x;
    const int lane = tid & 31, warp = tid >> 5;
    const int g = lane >> 2, tig = lane & 3;
    const int qm = (warp & 3) << 4;      // warp q-row base
    const int wn = (warp >> 2) << 5;     // warp n-col base
    const int wcol = warp >> 2;

    const int lr = tid >> 4;             // 0..15
    const int lc4 = (tid & 15) << 2;     // half col (0..60)
    const int lc2 = (tid & 15) << 1;     // half2 col

    // ---- Q block [row][k] half2 ----
    {
        const float* qbase = qkv + (size_t)(b * Td + q0) * QKVN + h * HDd;
        #pragma unroll
        for (int i = 0; i < 4; i++) {
            int r = lr + (i << 4);
            *(uint2*)&QF[r * TP2 + lc2] =
                pack4(*(const float4*)&qbase[(size_t)r * QKVN + lc4]);
        }
    }

    float o[4][4] = {};
    float m0_ = -1e30f, m1_ = -1e30f, l0_ = 0.f, l1_ = 0.f;
    const float scale = 0.125f;
    const int r0 = qm + g, r1 = qm + g + 8;

    for (int kt = 0; kt < ntiles; kt++) {
        const int D = q0 - (kt << 6);
        const bool haveLo = (D != 0);

        // ---- K tile + rel band ----
        {
            const float* kbase = qkv + (size_t)(b * Td + (kt << 6)) * QKVN + Cd + h * HDd;
            #pragma unroll
            for (int i = 0; i < 4; i++) {
                int r = lr + (i << 4);
                *(uint2*)&KF[r * TP2 + lc2] =
                    pack4(*(const float4*)&kbase[(size_t)r * QKVN + lc4]);
            }
            #pragma unroll
            for (int i = 0; i < 8; i++) {
                int rr = lr + (i << 4);              // 0..127
                int delta = D - 64 + rr;
                if (delta >= 0) {
                    float4 v = *(const float4*)&rel_emb[(size_t)delta * Cd + h * HDd + lc4];
                    *(uint2*)&RF[(rr >> 6) * 2304 + (rr & 63) * TP2 + lc2] = pack4(v);
                }
            }
        }
        __syncthreads();   // (a)

        // ---- MMA: S = Q K^T ; P = Q rel^T ----
        float cS[4][4] = {};
        float cP1[4][4] = {};
        float cP0[4][4] = {};
        #pragma unroll
        for (int ks = 0; ks < 4; ks++) {
            const int ko = ks << 3;
            unsigned a0 = QF[r0 * TP2 + ko + tig];
            unsigned a1 = QF[r1 * TP2 + ko + tig];
            unsigned a2 = QF[r0 * TP2 + ko + 4 + tig];
            unsigned a3 = QF[r1 * TP2 + ko + 4 + tig];
            #pragma unroll
            for (int j = 0; j < 4; j++) {
                int nr = wn + (j << 3) + g;
                unsigned bk0 = KF[nr * TP2 + ko + tig];
                unsigned bk1 = KF[nr * TP2 + ko + 4 + tig];
                mma_f16(cS[j], a0, a1, a2, a3, bk0, bk1);
                unsigned bh0 = RF[2304 + nr * TP2 + ko + tig];
                unsigned bh1 = RF[2304 + nr * TP2 + ko + 4 + tig];
                mma_f16(cP1[j], a0, a1, a2, a3, bh0, bh1);
                if (haveLo) {
                    unsigned bl0 = RF[nr * TP2 + ko + tig];
                    unsigned bl1 = RF[nr * TP2 + ko + 4 + tig];
                    mma_f16(cP0[j], a0, a1, a2, a3, bl0, bl1);
                }
            }
        }
        // write pcat (rel bias band of 128 deltas per q row)
        #pragma unroll
        for (int j = 0; j < 4; j++) {
            int col = wn + (j << 3) + (tig << 1);
            if (haveLo) {
                *(float2*)&pcat[r0 * PCP + col] = make_float2(cP0[j][0], cP0[j][1]);
                *(float2*)&pcat[r1 * PCP + col] = make_float2(cP0[j][2], cP0[j][3]);
            }
            *(float2*)&pcat[r0 * PCP + 64 + col] = make_float2(cP1[j][0], cP1[j][1]);
            *(float2*)&pcat[r1 * PCP + 64 + col] = make_float2(cP1[j][2], cP1[j][3]);
        }
        __syncthreads();   // (b): pcat visible; K/rel reads done

        // ---- V tile transposed [d][key] halfs into RF slot 0 ----
        {
            __half* VH = (__half*)RF;
            const float* vbase = qkv + (size_t)(b * Td + (kt << 6)) * QKVN + 2 * Cd + h * HDd;
            #pragma unroll
            for (int i = 0; i < 4; i++) {
                int key = lr + (i << 4);
                float4 v = *(const float4*)&vbase[(size_t)key * QKVN + lc4];
                VH[(lc4 + 0) * 72 + key] = __float2half_rn(v.x);
                VH[(lc4 + 1) * 72 + key] = __float2half_rn(v.y);
                VH[(lc4 + 2) * 72 + key] = __float2half_rn(v.z);
                VH[(lc4 + 3) * 72 + key] = __float2half_rn(v.w);
            }
        }

        // ---- scores in registers: mask + bias + scale ----
        float s_[4][4];
        #pragma unroll
        for (int j = 0; j < 4; j++) {
            #pragma unroll
            for (int u = 0; u < 2; u++) {
                int c = wn + (j << 3) + (tig << 1) + u;
                s_[j][u] = (r0 - c + D >= 0)
                    ? (cS[j][u] + pcat[r0 * PCP + 64 + r0 - c]) * scale : -1e30f;
                s_[j][2 + u] = (r1 - c + D >= 0)
                    ? (cS[j][2 + u] + pcat[r1 * PCP + 64 + r1 - c]) * scale : -1e30f;
            }
        }
        float mx0 = -1e30f, mx1 = -1e30f;
        #pragma unroll
        for (int j = 0; j < 4; j++) {
            mx0 = fmaxf(mx0, fmaxf(s_[j][0], s_[j][1]));
            mx1 = fmaxf(mx1, fmaxf(s_[j][2], s_[j][3]));
        }
        #pragma unroll
        for (int oo = 1; oo <= 2; oo <<= 1) {
            mx0 = fmaxf(mx0, __shfl_xor_sync(0xffffffffu, mx0, oo));
            mx1 = fmaxf(mx1, __shfl_xor_sync(0xffffffffu, mx1, oo));
        }
        if (tig == 0) { pm[wcol * 64 + r0] = mx0; pm[wcol * 64 + r1] = mx1; }
        __syncthreads();   // (c)

        float mn0 = fmaxf(m0_, fmaxf(mx0, pm[(1 - wcol) * 64 + r0]));
        float mn1 = fmaxf(m1_, fmaxf(mx1, pm[(1 - wcol) * 64 + r1]));
        float al0 = __expf(m0_ - mn0), al1 = __expf(m1_ - mn1);
        m0_ = mn0; m1_ = mn1;

        float sum0 = 0.f, sum1 = 0.f;
        #pragma unroll
        for (int j = 0; j < 4; j++) {
            float p00 = __expf(s_[j][0] - mn0);
            float p01 = __expf(s_[j][1] - mn0);
            float p10 = __expf(s_[j][2] - mn1);
            float p11 = __expf(s_[j][3] - mn1);
            sum0 += p00 + p01; sum1 += p10 + p11;
            int cw = (wn >> 1) + (j << 2) + tig;     // half2 column
            PF[r0 * TP2 + cw] = f2h2(p00, p01);
            PF[r1 * TP2 + cw] = f2h2(p10, p11);
        }
        #pragma unroll
        for (int oo = 1; oo <= 2; oo <<= 1) {
            sum0 += __shfl_xor_sync(0xffffffffu, sum0, oo);
            sum1 += __shfl_xor_sync(0xffffffffu, sum1, oo);
        }
        if (tig == 0) { ps[wcol * 64 + r0] = sum0; ps[wcol * 64 + r1] = sum1; }
        __syncthreads();   // (d): P + sums + V visible

        l0_ = l0_ * al0 + sum0 + ps[(1 - wcol) * 64 + r0];
        l1_ = l1_ * al1 + sum1 + ps[(1 - wcol) * 64 + r1];

        #pragma unroll
        for (int j = 0; j < 4; j++) {
            o[j][0] *= al0; o[j][1] *= al0;
            o[j][2] *= al1; o[j][3] *= al1;
        }
        // ---- O += P @ V ----
        #pragma unroll
        for (int ks = 0; ks < 4; ks++) {
            const int ko = ks << 3;
            unsigned a0 = PF[r0 * TP2 + ko + tig];
            unsigned a1 = PF[r1 * TP2 + ko + tig];
            unsigned a2 = PF[r0 * TP2 + ko + 4 + tig];
            unsigned a3 = PF[r1 * TP2 + ko + 4 + tig];
            #pragma unroll
            for (int j = 0; j < 4; j++) {
                int nr = wn + (j << 3) + g;           // d row in V^T
                unsigned b0 = RF[nr * TP2 + ko + tig];
                unsigned b1 = RF[nr * TP2 + ko + 4 + tig];
                mma_f16(o[j], a0, a1, a2, a3, b0, b1);
            }
        }
        __syncthreads();   // (e)
    }

    // ---- finalize ----
    {
        float inv0 = 1.0f / l0_, inv1 = 1.0f / l1_;
        int row = b * Td + q0 + r0;
        #pragma unroll
        for (int j = 0; j < 4; j++) {
            int col = h * HDd + wn + (j << 3) + (tig << 1);
            *(float2*)&yout[(size_t)row * Cd + col] =
                make_float2(o[j][0] * inv0, o[j][1] * inv0);
            *(float2*)&yout[(size_t)(row + 8) * Cd + col] =
                make_float2(o[j][2] * inv1, o[j][3] * inv1);
        }
    }
}

// ---------------------------------------------------------------------------
extern "C" void kernel_launch(void* const* d_in, const int* in_sizes, int n_in,
                              void* d_out, int out_size)
{
    const float* x      = (const float*)d_in[0];
    const float* w_attn = (const float*)d_in[1];
    const float* b_attn = (const float*)d_in[2];
    const float* w_proj = (const float*)d_in[3];
    const float* b_proj = (const float*)d_in[4];
    const float* qg     = (const float*)d_in[5];
    const float* qbeta  = (const float*)d_in[6];
    const float* kg     = (const float*)d_in[7];
    const float* kbeta  = (const float*)d_in[8];
    const float* rel    = (const float*)d_in[9];
    float* out = (float*)d_out;

    float *qkv_p, *y_p;
    cudaGetSymbolAddress((void**)&qkv_p, g_qkv);
    cudaGetSymbolAddress((void**)&y_p, g_y);

    cudaFuncSetAttribute(attn_kernel,
                         cudaFuncAttributeMaxDynamicSharedMemorySize, ATTN_SMEM);

    // 1) QKV projection
    {
        dim3 grid(QKVN / 64, Md / 128);
        sgemm_bias_kernel<128><<<grid, 256>>>(x, w_attn, b_attn, qkv_p, Cd, QKVN);
    }
    // 2) LayerNorm q,k in place
    ln_qk_kernel<<<Md, 256>>>(qkv_p, qg, qbeta, kg, kbeta);
    // 3) Flash attention
    attn_kernel<<<Bd * NHd * (Td / 64), 256, ATTN_SMEM>>>(qkv_p, rel, y_p);
    // 4) Output projection
    {
        dim3 grid(Cd / 64, Md / 64);
        sgemm_bias_kernel<64><<<grid, 256>>>(y_p, w_proj, b_proj, out, Cd, Cd);
    }
}

// round 13
// speedup vs baseline: 2.1531x; 1.0234x over previous
#include <cuda_runtime.h>
#include <cuda_fp16.h>

#define Bd 8
#define Td 512
#define Cd 512
#define NHd 8
#define HDd 64
#define Md (Bd * Td)            // 4096
#define QKVN (3 * Cd)           // 1536

__device__ float g_qkv[Md * QKVN];
__device__ float g_y[Md * Cd];

// pack two floats into half2 bits (lo, hi)
__device__ __forceinline__ unsigned f2h2(float lo, float hi) {
    unsigned u;
    asm("cvt.rn.f16x2.f32 %0, %1, %2;" : "=r"(u) : "f"(hi), "f"(lo));
    return u;
}
__device__ __forceinline__ uint2 pack4(float4 v) {
    return make_uint2(f2h2(v.x, v.y), f2h2(v.z, v.w));
}
__device__ __forceinline__ void mma_f16(float c[4],
    unsigned a0, unsigned a1, unsigned a2, unsigned a3,
    unsigned b0, unsigned b1)
{
    asm volatile(
        "mma.sync.aligned.m16n8k16.row.col.f32.f16.f16.f32 "
        "{%0,%1,%2,%3}, {%4,%5,%6,%7}, {%8,%9}, {%0,%1,%2,%3};"
        : "+f"(c[0]), "+f"(c[1]), "+f"(c[2]), "+f"(c[3])
        : "r"(a0), "r"(a1), "r"(a2), "r"(a3), "r"(b0), "r"(b1));
}

__device__ __forceinline__ unsigned smaddr(const void* p) {
    return (unsigned)__cvta_generic_to_shared(p);
}
__device__ __forceinline__ void ldsm_x4(unsigned& r0, unsigned& r1,
                                        unsigned& r2, unsigned& r3, unsigned addr) {
    asm volatile("ldmatrix.sync.aligned.m8n8.x4.shared.b16 {%0,%1,%2,%3}, [%4];"
        : "=r"(r0), "=r"(r1), "=r"(r2), "=r"(r3) : "r"(addr));
}
// A-fragment m16xk16 at rows rb..rb+15, halfs ko..ko+15
__device__ __forceinline__ void ldA(unsigned a[4], const __half* base, int pitch,
                                    int rb, int ko, int lane) {
    int row = rb + (lane & 15);
    int kk = ko + ((lane >> 4) << 3);
    unsigned addr = smaddr(base + row * pitch + kk);
    ldsm_x4(a[0], a[1], a[2], a[3], addr);
}
// B-fragments for TWO n8 subtiles (rows nb..nb+15), halfs ko..ko+15
// out: b[0],b[1] = subtile nb; b[2],b[3] = subtile nb+8
__device__ __forceinline__ void ldB2(unsigned b[4], const __half* base, int pitch,
                                     int nb, int ko, int lane) {
    int row = nb + (lane & 7) + ((lane >> 4) << 3);
    int kk = ko + (((lane >> 3) & 1) << 3);
    unsigned addr = smaddr(base + row * pitch + kk);
    ldsm_x4(b[0], b[1], b[2], b[3], addr);
}

// ---------------------------------------------------------------------------
// fp16 SGEMM: out[m,n] = A[m,:]·W[n,:] + bias[n]
// BM x 64 tile, BK=32, 256 threads, warps 4(M)x2(N). Pitch 40 halfs.
// ---------------------------------------------------------------------------
#define GP2 20
#define GPH 40
template<int BM>
__global__ __launch_bounds__(256) void sgemm_bias_kernel(
    const float* __restrict__ A, const float* __restrict__ W,
    const float* __restrict__ bias, float* __restrict__ out,
    int Kdim, int Ndim)
{
    constexpr int MI = BM / 64;
    constexpr int AL = BM / 32;
    __shared__ __align__(16) unsigned As[BM * GP2];
    __shared__ __align__(16) unsigned Bs[64 * GP2];
    const __half* AsH = (const __half*)As;
    const __half* BsH = (const __half*)Bs;
    const int tid = threadIdx.x;
    const int lane = tid & 31, warp = tid >> 5;
    const int g = lane >> 2, tig = lane & 3;
    const int wm = (warp & 3) * (BM / 4);
    const int wn = (warp >> 2) << 5;
    const int m0 = blockIdx.y * BM, n0 = blockIdx.x << 6;

    const int lrow = tid >> 3;             // 0..31
    const int lk4 = (tid & 7) << 2;        // halfs 0,4..28
    const int lk2 = lk4 >> 1;              // half2 idx

    float c[MI][4][4] = {};
    float4 avr[AL], bvr[2];

    #pragma unroll
    for (int i = 0; i < AL; i++)
        avr[i] = *(const float4*)&A[(size_t)(m0 + lrow + (i << 5)) * Kdim + lk4];
    #pragma unroll
    for (int i = 0; i < 2; i++)
        bvr[i] = *(const float4*)&W[(size_t)(n0 + lrow + (i << 5)) * Kdim + lk4];

    for (int k0 = 0; k0 < Kdim; k0 += 32) {
        #pragma unroll
        for (int i = 0; i < AL; i++)
            *(uint2*)&As[(lrow + (i << 5)) * GP2 + lk2] = pack4(avr[i]);
        #pragma unroll
        for (int i = 0; i < 2; i++)
            *(uint2*)&Bs[(lrow + (i << 5)) * GP2 + lk2] = pack4(bvr[i]);
        __syncthreads();

        if (k0 + 32 < Kdim) {
            #pragma unroll
            for (int i = 0; i < AL; i++)
                avr[i] = *(const float4*)&A[(size_t)(m0 + lrow + (i << 5)) * Kdim + k0 + 32 + lk4];
            #pragma unroll
            for (int i = 0; i < 2; i++)
                bvr[i] = *(const float4*)&W[(size_t)(n0 + lrow + (i << 5)) * Kdim + k0 + 32 + lk4];
        }

        #pragma unroll
        for (int ks = 0; ks < 2; ks++) {           // two k16 steps
            const int ko = ks << 4;                // half offset
            unsigned a[MI][4];
            #pragma unroll
            for (int i = 0; i < MI; i++)
                ldA(a[i], AsH, GPH, wm + (i << 4), ko, lane);
            unsigned b[2][4];
            ldB2(b[0], BsH, GPH, wn, ko, lane);
            ldB2(b[1], BsH, GPH, wn + 16, ko, lane);
            #pragma unroll
            for (int j = 0; j < 4; j++) {
                unsigned b0 = b[j >> 1][(j & 1) << 1];
                unsigned b1 = b[j >> 1][((j & 1) << 1) + 1];
                #pragma unroll
                for (int i = 0; i < MI; i++)
                    mma_f16(c[i][j], a[i][0], a[i][1], a[i][2], a[i][3], b0, b1);
            }
        }
        __syncthreads();
    }

    #pragma unroll
    for (int i = 0; i < MI; i++) {
        #pragma unroll
        for (int j = 0; j < 4; j++) {
            int row = m0 + wm + (i << 4) + g;
            int col = n0 + wn + (j << 3) + (tig << 1);
            float b0 = bias[col], b1 = bias[col + 1];
            *(float2*)&out[(size_t)row * Ndim + col] =
                make_float2(c[i][j][0] + b0, c[i][j][1] + b1);
            *(float2*)&out[(size_t)(row + 8) * Ndim + col] =
                make_float2(c[i][j][2] + b0, c[i][j][3] + b1);
        }
    }
}

// ---------------------------------------------------------------------------
// LayerNorm q,k (unchanged)
// ---------------------------------------------------------------------------
__global__ __launch_bounds__(256) void ln_qk_kernel(
    float* __restrict__ qkv,
    const float* __restrict__ qg, const float* __restrict__ qb,
    const float* __restrict__ kg, const float* __restrict__ kb)
{
    const int bt = blockIdx.x;
    float* row = qkv + (size_t)bt * QKVN;
    const int tid = threadIdx.x;
    const int lane = tid & 31, w = tid >> 5;
    __shared__ float sh_s[8], sh_ss[8];

    #pragma unroll
    for (int seg = 0; seg < 2; seg++) {
        float* p = row + seg * Cd;
        const float* gam = seg ? kg : qg;
        const float* bet = seg ? kb : qb;
        float x0 = p[tid], x1 = p[tid + 256];
        float s = x0 + x1;
        float ss = x0 * x0 + x1 * x1;
        #pragma unroll
        for (int o = 16; o; o >>= 1) {
            s  += __shfl_xor_sync(0xffffffffu, s, o);
            ss += __shfl_xor_sync(0xffffffffu, ss, o);
        }
        if (lane == 0) { sh_s[w] = s; sh_ss[w] = ss; }
        __syncthreads();
        float tot = 0.f, tot2 = 0.f;
        #pragma unroll
        for (int i = 0; i < 8; i++) { tot += sh_s[i]; tot2 += sh_ss[i]; }
        float mu = tot * (1.0f / 512.0f);
        float var = tot2 * (1.0f / 512.0f) - mu * mu;
        float rstd = rsqrtf(var + 1e-5f);
        p[tid]       = (x0 - mu) * rstd * gam[tid]       + bet[tid];
        p[tid + 256] = (x1 - mu) * rstd * gam[tid + 256] + bet[tid + 256];
        __syncthreads();
    }
}

// ---------------------------------------------------------------------------
// Flash attention, fp16 MMA + ldmatrix operands, register-resident softmax.
// Layouts identical to R12 (pitch 72 halfs).
// ---------------------------------------------------------------------------
#define TP2 36
#define TPH 72
#define PCP 132
#define ATTN_SMEM ((2304 * 4 + 4608 + 8448 + 256) * 4)

__global__ __launch_bounds__(256, 2) void attn_kernel(
    const float* __restrict__ qkv,
    const float* __restrict__ rel_emb,
    float* __restrict__ yout)
{
    const int blk = blockIdx.x;
    const int qb = 7 - (blk & 7);        // heavy blocks first
    const int h  = (blk >> 3) & 7;
    const int b  = blk >> 6;
    const int q0 = qb << 6;
    const int ntiles = qb + 1;

    extern __shared__ unsigned smu[];
    unsigned* QF = smu;                  // Q [row][k] half2
    unsigned* RF = smu + 2304;           // rel tiles x2; V (transposed) reuses slot0
    unsigned* KF = smu + 6912;           // K [key][d] half2
    unsigned* PF = smu + 9216;           // probabilities [row][key] half2
    float* pcat = (float*)(smu + 11520);
    float* pm   = (float*)(smu + 19968);
    float* ps   = (float*)(smu + 20096);
    const __half* QH = (const __half*)QF;
    const __half* RH = (const __half*)RF;
    const __half* KH = (const __half*)KF;
    const __half* PH = (const __half*)PF;

    const int tid = threadIdx.x;
    const int lane = tid & 31, warp = tid >> 5;
    const int g = lane >> 2, tig = lane & 3;
    const int qm = (warp & 3) << 4;      // warp q-row base
    const int wn = (warp >> 2) << 5;     // warp n-col base
    const int wcol = warp >> 2;

    const int lr = tid >> 4;             // 0..15
    const int lc4 = (tid & 15) << 2;     // half col (0..60)
    const int lc2 = (tid & 15) << 1;     // half2 col

    // ---- Q block [row][k] half2 ----
    {
        const float* qbase = qkv + (size_t)(b * Td + q0) * QKVN + h * HDd;
        #pragma unroll
        for (int i = 0; i < 4; i++) {
            int r = lr + (i << 4);
            *(uint2*)&QF[r * TP2 + lc2] =
                pack4(*(const float4*)&qbase[(size_t)r * QKVN + lc4]);
        }
    }

    float o[4][4] = {};
    float m0_ = -1e30f, m1_ = -1e30f, l0_ = 0.f, l1_ = 0.f;
    const float scale = 0.125f;
    const int r0 = qm + g, r1 = qm + g + 8;

    for (int kt = 0; kt < ntiles; kt++) {
        const int D = q0 - (kt << 6);
        const bool haveLo = (D != 0);

        // ---- K tile + rel band ----
        {
            const float* kbase = qkv + (size_t)(b * Td + (kt << 6)) * QKVN + Cd + h * HDd;
            #pragma unroll
            for (int i = 0; i < 4; i++) {
                int r = lr + (i << 4);
                *(uint2*)&KF[r * TP2 + lc2] =
                    pack4(*(const float4*)&kbase[(size_t)r * QKVN + lc4]);
            }
            #pragma unroll
            for (int i = 0; i < 8; i++) {
                int rr = lr + (i << 4);              // 0..127
                int delta = D - 64 + rr;
                if (delta >= 0) {
                    float4 v = *(const float4*)&rel_emb[(size_t)delta * Cd + h * HDd + lc4];
                    *(uint2*)&RF[(rr >> 6) * 2304 + (rr & 63) * TP2 + lc2] = pack4(v);
                }
            }
        }
        __syncthreads();   // (a)

        // ---- MMA: S = Q K^T ; P = Q rel^T ----
        float cS[4][4] = {};
        float cP1[4][4] = {};
        float cP0[4][4] = {};
        #pragma unroll
        for (int ks = 0; ks < 4; ks++) {
            const int ko = ks << 4;                  // half offset
            unsigned aq[4];
            ldA(aq, QH, TPH, qm, ko, lane);
            unsigned bk[2][4], bh[2][4], bl[2][4];
            ldB2(bk[0], KH, TPH, wn, ko, lane);
            ldB2(bk[1], KH, TPH, wn + 16, ko, lane);
            ldB2(bh[0], RH + 4608, TPH, wn, ko, lane);
            ldB2(bh[1], RH + 4608, TPH, wn + 16, ko, lane);
            if (haveLo) {
                ldB2(bl[0], RH, TPH, wn, ko, lane);
                ldB2(bl[1], RH, TPH, wn + 16, ko, lane);
            }
            #pragma unroll
            for (int j = 0; j < 4; j++) {
                int p = j >> 1, q = (j & 1) << 1;
                mma_f16(cS[j], aq[0], aq[1], aq[2], aq[3], bk[p][q], bk[p][q + 1]);
                mma_f16(cP1[j], aq[0], aq[1], aq[2], aq[3], bh[p][q], bh[p][q + 1]);
                if (haveLo)
                    mma_f16(cP0[j], aq[0], aq[1], aq[2], aq[3], bl[p][q], bl[p][q + 1]);
            }
        }
        // write pcat (rel bias band of 128 deltas per q row)
        #pragma unroll
        for (int j = 0; j < 4; j++) {
            int col = wn + (j << 3) + (tig << 1);
            if (haveLo) {
                *(float2*)&pcat[r0 * PCP + col] = make_float2(cP0[j][0], cP0[j][1]);
                *(float2*)&pcat[r1 * PCP + col] = make_float2(cP0[j][2], cP0[j][3]);
            }
            *(float2*)&pcat[r0 * PCP + 64 + col] = make_float2(cP1[j][0], cP1[j][1]);
            *(float2*)&pcat[r1 * PCP + 64 + col] = make_float2(cP1[j][2], cP1[j][3]);
        }
        __syncthreads();   // (b): pcat visible; K/rel reads done

        // ---- V tile transposed [d][key] halfs into RF slot 0 ----
        {
            __half* VH = (__half*)RF;
            const float* vbase = qkv + (size_t)(b * Td + (kt << 6)) * QKVN + 2 * Cd + h * HDd;
            #pragma unroll
            for (int i = 0; i < 4; i++) {
                int key = lr + (i << 4);
                float4 v = *(const float4*)&vbase[(size_t)key * QKVN + lc4];
                VH[(lc4 + 0) * TPH + key] = __float2half_rn(v.x);
                VH[(lc4 + 1) * TPH + key] = __float2half_rn(v.y);
                VH[(lc4 + 2) * TPH + key] = __float2half_rn(v.z);
                VH[(lc4 + 3) * TPH + key] = __float2half_rn(v.w);
            }
        }

        // ---- scores in registers: mask + bias + scale ----
        float s_[4][4];
        #pragma unroll
        for (int j = 0; j < 4; j++) {
            #pragma unroll
            for (int u = 0; u < 2; u++) {
                int c = wn + (j << 3) + (tig << 1) + u;
                s_[j][u] = (r0 - c + D >= 0)
                    ? (cS[j][u] + pcat[r0 * PCP + 64 + r0 - c]) * scale : -1e30f;
                s_[j][2 + u] = (r1 - c + D >= 0)
                    ? (cS[j][2 + u] + pcat[r1 * PCP + 64 + r1 - c]) * scale : -1e30f;
            }
        }
        float mx0 = -1e30f, mx1 = -1e30f;
        #pragma unroll
        for (int j = 0; j < 4; j++) {
            mx0 = fmaxf(mx0, fmaxf(s_[j][0], s_[j][1]));
            mx1 = fmaxf(mx1, fmaxf(s_[j][2], s_[j][3]));
        }
        #pragma unroll
        for (int oo = 1; oo <= 2; oo <<= 1) {
            mx0 = fmaxf(mx0, __shfl_xor_sync(0xffffffffu, mx0, oo));
            mx1 = fmaxf(mx1, __shfl_xor_sync(0xffffffffu, mx1, oo));
        }
        if (tig == 0) { pm[wcol * 64 + r0] = mx0; pm[wcol * 64 + r1] = mx1; }
        __syncthreads();   // (c)

        float mn0 = fmaxf(m0_, fmaxf(mx0, pm[(1 - wcol) * 64 + r0]));
        float mn1 = fmaxf(m1_, fmaxf(mx1, pm[(1 - wcol) * 64 + r1]));
        float al0 = __expf(m0_ - mn0), al1 = __expf(m1_ - mn1);
        m0_ = mn0; m1_ = mn1;

        float sum0 = 0.f, sum1 = 0.f;
        #pragma unroll
        for (int j = 0; j < 4; j++) {
            float p00 = __expf(s_[j][0] - mn0);
            float p01 = __expf(s_[j][1] - mn0);
            float p10 = __expf(s_[j][2] - mn1);
            float p11 = __expf(s_[j][3] - mn1);
            sum0 += p00 + p01; sum1 += p10 + p11;
            int cw = (wn >> 1) + (j << 2) + tig;     // half2 column
            PF[r0 * TP2 + cw] = f2h2(p00, p01);
            PF[r1 * TP2 + cw] = f2h2(p10, p11);
        }
        #pragma unroll
        for (int oo = 1; oo <= 2; oo <<= 1) {
            sum0 += __shfl_xor_sync(0xffffffffu, sum0, oo);
            sum1 += __shfl_xor_sync(0xffffffffu, sum1, oo);
        }
        if (tig == 0) { ps[wcol * 64 + r0] = sum0; ps[wcol * 64 + r1] = sum1; }
        __syncthreads();   // (d): P + sums + V visible

        l0_ = l0_ * al0 + sum0 + ps[(1 - wcol) * 64 + r0];
        l1_ = l1_ * al1 + sum1 + ps[(1 - wcol) * 64 + r1];

        #pragma unroll
        for (int j = 0; j < 4; j++) {
            o[j][0] *= al0; o[j][1] *= al0;
            o[j][2] *= al1; o[j][3] *= al1;
        }
        // ---- O += P @ V ----
        #pragma unroll
        for (int ks = 0; ks < 4; ks++) {
            const int ko = ks << 4;                  // key offset in halfs
            unsigned ap[4];
            ldA(ap, PH, TPH, qm, ko, lane);
            unsigned bv[2][4];
            ldB2(bv[0], RH, TPH, wn, ko, lane);
            ldB2(bv[1], RH, TPH, wn + 16, ko, lane);
            #pragma unroll
            for (int j = 0; j < 4; j++) {
                int p = j >> 1, q = (j & 1) << 1;
                mma_f16(o[j], ap[0], ap[1], ap[2], ap[3], bv[p][q], bv[p][q + 1]);
            }
        }
        __syncthreads();   // (e)
    }

    // ---- finalize ----
    {
        float inv0 = 1.0f / l0_, inv1 = 1.0f / l1_;
        int row = b * Td + q0 + r0;
        #pragma unroll
        for (int j = 0; j < 4; j++) {
            int col = h * HDd + wn + (j << 3) + (tig << 1);
            *(float2*)&yout[(size_t)row * Cd + col] =
                make_float2(o[j][0] * inv0, o[j][1] * inv0);
            *(float2*)&yout[(size_t)(row + 8) * Cd + col] =
                make_float2(o[j][2] * inv1, o[j][3] * inv1);
        }
    }
}

// ---------------------------------------------------------------------------
extern "C" void kernel_launch(void* const* d_in, const int* in_sizes, int n_in,
                              void* d_out, int out_size)
{
    const float* x      = (const float*)d_in[0];
    const float* w_attn = (const float*)d_in[1];
    const float* b_attn = (const float*)d_in[2];
    const float* w_proj = (const float*)d_in[3];
    const float* b_proj = (const float*)d_in[4];
    const float* qg     = (const float*)d_in[5];
    const float* qbeta  = (const float*)d_in[6];
    const float* kg     = (const float*)d_in[7];
    const float* kbeta  = (const float*)d_in[8];
    const float* rel    = (const float*)d_in[9];
    float* out = (float*)d_out;

    float *qkv_p, *y_p;
    cudaGetSymbolAddress((void**)&qkv_p, g_qkv);
    cudaGetSymbolAddress((void**)&y_p, g_y);

    cudaFuncSetAttribute(attn_kernel,
                         cudaFuncAttributeMaxDynamicSharedMemorySize, ATTN_SMEM);

    // 1) QKV projection
    {
        dim3 grid(QKVN / 64, Md / 128);
        sgemm_bias_kernel<128><<<grid, 256>>>(x, w_attn, b_attn, qkv_p, Cd, QKVN);
    }
    // 2) LayerNorm q,k in place
    ln_qk_kernel<<<Md, 256>>>(qkv_p, qg, qbeta, kg, kbeta);
    // 3) Flash attention
    attn_kernel<<<Bd * NHd * (Td / 64), 256, ATTN_SMEM>>>(qkv_p, rel, y_p);
    // 4) Output projection
    {
        dim3 grid(Cd / 64, Md / 64);
        sgemm_bias_kernel<64><<<grid, 256>>>(y_p, w_proj, b_proj, out, Cd, Cd);
    }
}